// round 1
// baseline (speedup 1.0000x reference)
#include <cuda_runtime.h>
#include <math.h>

#define BB 4
#define TT 2048
#define CC 1024
#define HH 64
#define NROWS (BB * TT)   // 8192

// Scratch for q, k, v projections (2 MB each) — __device__ globals per alloc rules.
__device__ float g_q[NROWS * HH];
__device__ float g_k[NROWS * HH];
__device__ float g_v[NROWS * HH];

// ---------------------------------------------------------------------------
// Kernel 1: fused QKV projection.  out[r, n] = sum_c x[r, c] * W[c, n]
// Tiled SGEMM: BM=64, BN=64(=HH), BK=16, 256 threads, 4x4 register tile.
// grid = (NROWS/64, 3)  — blockIdx.y selects Wq/Wk/Wv.
// ---------------------------------------------------------------------------
__global__ __launch_bounds__(256) void proj_kernel(
    const float* __restrict__ x,
    const float* __restrict__ Wq,
    const float* __restrict__ Wk,
    const float* __restrict__ Wv)
{
    const float* W = (blockIdx.y == 0) ? Wq : (blockIdx.y == 1) ? Wk : Wv;
    float* out     = (blockIdx.y == 0) ? g_q : (blockIdx.y == 1) ? g_k : g_v;

    __shared__ float As[16][68];   // [k][m], padded for float4-aligned conflict-light access
    __shared__ float Bs[16][64];   // [k][n]

    const int tid  = threadIdx.x;
    const int tx   = tid % 16;          // n-tile
    const int ty   = tid / 16;          // m-tile
    const int row0 = blockIdx.x * 64;

    // load lanes
    const int lak = tid % 16;           // k for A loads
    const int lam = tid / 16;           // base m for A loads
    const int lbn = tid % 64;           // n for B loads
    const int lbk = tid / 64;           // base k for B loads

    float acc[4][4] = {};

    for (int k0 = 0; k0 < CC; k0 += 16) {
        __syncthreads();
#pragma unroll
        for (int i = 0; i < 4; i++)
            As[lak][lam + 16 * i] = x[(row0 + lam + 16 * i) * CC + k0 + lak];
#pragma unroll
        for (int i = 0; i < 4; i++)
            Bs[lbk + 4 * i][lbn] = W[(k0 + lbk + 4 * i) * HH + lbn];
        __syncthreads();

#pragma unroll
        for (int k = 0; k < 16; k++) {
            float4 a4 = *(const float4*)&As[k][ty * 4];
            float4 b4 = *(const float4*)&Bs[k][tx * 4];
            float av[4] = {a4.x, a4.y, a4.z, a4.w};
            float bv[4] = {b4.x, b4.y, b4.z, b4.w};
#pragma unroll
            for (int i = 0; i < 4; i++)
#pragma unroll
                for (int j = 0; j < 4; j++)
                    acc[i][j] += av[i] * bv[j];
        }
    }

#pragma unroll
    for (int i = 0; i < 4; i++)
#pragma unroll
        for (int j = 0; j < 4; j++)
            out[(row0 + ty * 4 + i) * HH + tx * 4 + j] = acc[i][j];
}

// ---------------------------------------------------------------------------
// Kernel 2: causal attention with the reference's exact mask semantics:
//   s = (q . k) * H^-0.5 ;  if (col > row || s == 0.0f) s = -inf ;  softmax ; P@V
// Flash-style online softmax.
// Block: 128 threads (4 warps). Each block = 16 query rows of one batch.
//   warp w owns rows 4w..4w+3 ; lane l owns key-cols / out-dims {l, l+32}.
// Key loop: 64 keys per tile.
// grid = (TT/16, BB)
// ---------------------------------------------------------------------------
__global__ __launch_bounds__(128) void attn_kernel(float* __restrict__ out)
{
    const int b   = blockIdx.y;
    const int qs  = blockIdx.x * 16;
    const int tid = threadIdx.x;
    const int w   = tid / 32;
    const int l   = tid % 32;

    __shared__ float Qs[16][64];
    __shared__ float Ks[64][68];   // padded: float4 reads over c are conflict-free
    __shared__ float Vs[64][64];   // [key][dim]; reads Vs[j][l] are conflict-free
    __shared__ float Ps[4][4][64]; // per-warp P tile: [warp][row][key]

    const float* qb = g_q + b * TT * HH;
    const float* kb = g_k + b * TT * HH;
    const float* vb = g_v + b * TT * HH;

    // Load Q tile (stays for whole block)
    for (int idx = tid; idx < 16 * 64; idx += 128)
        Qs[idx / 64][idx % 64] = qb[(qs + idx / 64) * HH + (idx % 64)];

    float m[4], lsum[4], acc0[4], acc1[4];
#pragma unroll
    for (int i = 0; i < 4; i++) {
        m[i] = -INFINITY; lsum[i] = 0.f; acc0[i] = 0.f; acc1[i] = 0.f;
    }

    const int nkb = (qs + 16 + 63) / 64;   // key tiles needed for causal coverage

    for (int t = 0; t < nkb; t++) {
        __syncthreads();
        for (int idx = tid; idx < 64 * 64; idx += 128) {
            const int j = idx / 64, c = idx % 64;
            Ks[j][c] = kb[(t * 64 + j) * HH + c];
            Vs[j][c] = vb[(t * 64 + j) * HH + c];
        }
        __syncthreads();

        // ---- scores: s[i][{l, l+32}] = Q[row] . K[col] ----
        float s0[4] = {0.f, 0.f, 0.f, 0.f};
        float s1[4] = {0.f, 0.f, 0.f, 0.f};
#pragma unroll
        for (int c4 = 0; c4 < 16; c4++) {
            float4 k0 = *(const float4*)&Ks[l][c4 * 4];
            float4 k1 = *(const float4*)&Ks[l + 32][c4 * 4];
#pragma unroll
            for (int i = 0; i < 4; i++) {
                float4 q4 = *(const float4*)&Qs[w * 4 + i][c4 * 4];
                s0[i] += q4.x * k0.x + q4.y * k0.y + q4.z * k0.z + q4.w * k0.w;
                s1[i] += q4.x * k1.x + q4.y * k1.y + q4.z * k1.z + q4.w * k1.w;
            }
        }

        const int col0 = t * 64 + l;
        const int col1 = t * 64 + l + 32;

#pragma unroll
        for (int i = 0; i < 4; i++) {
            const int rowg = qs + w * 4 + i;
            float sc0 = s0[i] * 0.125f;   // H^-0.5 = 1/8
            float sc1 = s1[i] * 0.125f;
            // Faithful mask: tril, then exact-zero -> -inf
            if (col0 > rowg || sc0 == 0.0f) sc0 = -INFINITY;
            if (col1 > rowg || sc1 == 0.0f) sc1 = -INFINITY;

            // row max across the warp (each lane holds 2 cols of this row)
            float rmax = fmaxf(sc0, sc1);
#pragma unroll
            for (int off = 16; off > 0; off >>= 1)
                rmax = fmaxf(rmax, __shfl_xor_sync(0xffffffffu, rmax, off));

            const float mnew = fmaxf(m[i], rmax);
            const float f    = __expf(m[i] - mnew);   // exp(-inf)=0 on first tile
            const float p0   = __expf(sc0 - mnew);
            const float p1   = __expf(sc1 - mnew);

            float psum = p0 + p1;
#pragma unroll
            for (int off = 16; off > 0; off >>= 1)
                psum += __shfl_xor_sync(0xffffffffu, psum, off);

            lsum[i] = lsum[i] * f + psum;
            acc0[i] *= f;
            acc1[i] *= f;
            m[i] = mnew;

            Ps[w][i][l]      = p0;
            Ps[w][i][l + 32] = p1;
        }
        __syncwarp();

        // ---- P @ V : acc[i][d] += sum_j P[i][j] * V[j][d] ----
#pragma unroll 4
        for (int j = 0; j < 64; j++) {
            const float v0 = Vs[j][l];
            const float v1 = Vs[j][l + 32];
#pragma unroll
            for (int i = 0; i < 4; i++) {
                const float p = Ps[w][i][j];   // uniform per warp -> broadcast
                acc0[i] += p * v0;
                acc1[i] += p * v1;
            }
        }
        __syncwarp();
    }

#pragma unroll
    for (int i = 0; i < 4; i++) {
        const int rowg = qs + w * 4 + i;
        const float inv = 1.0f / lsum[i];
        out[(b * TT + rowg) * HH + l]      = acc0[i] * inv;
        out[(b * TT + rowg) * HH + l + 32] = acc1[i] * inv;
    }
}

// ---------------------------------------------------------------------------
extern "C" void kernel_launch(void* const* d_in, const int* in_sizes, int n_in,
                              void* d_out, int out_size)
{
    const float* x  = (const float*)d_in[0];
    const float* Wq = (const float*)d_in[1];
    const float* Wk = (const float*)d_in[2];
    const float* Wv = (const float*)d_in[3];
    float* out = (float*)d_out;

    proj_kernel<<<dim3(NROWS / 64, 3), 256>>>(x, Wq, Wk, Wv);
    attn_kernel<<<dim3(TT / 16, BB), 128>>>(out);
}

// round 2
// speedup vs baseline: 1.3706x; 1.3706x over previous
#include <cuda_runtime.h>
#include <math.h>

#define BB 4
#define TT 2048
#define CC 1024
#define HH 64
#define NROWS (BB * TT)   // 8192
#define QT 32             // query rows per phase

__device__ float g_q[NROWS * HH];
__device__ float g_k[NROWS * HH];
__device__ float g_v[NROWS * HH];

// ---------------------------------------------------------------------------
// Kernel 1: fused QKV projection (unchanged — already near FFMA-bound).
// ---------------------------------------------------------------------------
__global__ __launch_bounds__(256) void proj_kernel(
    const float* __restrict__ x,
    const float* __restrict__ Wq,
    const float* __restrict__ Wk,
    const float* __restrict__ Wv)
{
    const float* W = (blockIdx.y == 0) ? Wq : (blockIdx.y == 1) ? Wk : Wv;
    float* out     = (blockIdx.y == 0) ? g_q : (blockIdx.y == 1) ? g_k : g_v;

    __shared__ float As[16][68];
    __shared__ float Bs[16][64];

    const int tid  = threadIdx.x;
    const int tx   = tid % 16;
    const int ty   = tid / 16;
    const int row0 = blockIdx.x * 64;

    const int lak = tid % 16;
    const int lam = tid / 16;
    const int lbn = tid % 64;
    const int lbk = tid / 64;

    float acc[4][4] = {};

    for (int k0 = 0; k0 < CC; k0 += 16) {
        __syncthreads();
#pragma unroll
        for (int i = 0; i < 4; i++)
            As[lak][lam + 16 * i] = x[(row0 + lam + 16 * i) * CC + k0 + lak];
#pragma unroll
        for (int i = 0; i < 4; i++)
            Bs[lbk + 4 * i][lbn] = W[(k0 + lbk + 4 * i) * HH + lbn];
        __syncthreads();

#pragma unroll
        for (int k = 0; k < 16; k++) {
            float4 a4 = *(const float4*)&As[k][ty * 4];
            float4 b4 = *(const float4*)&Bs[k][tx * 4];
            float av[4] = {a4.x, a4.y, a4.z, a4.w};
            float bv[4] = {b4.x, b4.y, b4.z, b4.w};
#pragma unroll
            for (int i = 0; i < 4; i++)
#pragma unroll
                for (int j = 0; j < 4; j++)
                    acc[i][j] += av[i] * bv[j];
        }
    }

#pragma unroll
    for (int i = 0; i < 4; i++)
#pragma unroll
        for (int j = 0; j < 4; j++)
            out[(row0 + ty * 4 + i) * HH + tx * 4 + j] = acc[i][j];
}

// ---------------------------------------------------------------------------
// Kernel 2: causal attention, work-paired + register-prefetch double buffer.
// Block = 256 threads (8 warps). Two phases: q-tile p and q-tile 63-p (32 rows
// each) -> ~constant 33 key-tiles of work per block. Grid (32, BB) = 128.
// Warp w owns rows 4w..4w+3 of the phase tile; lane l owns cols/dims {l,l+32}.
// Mask is the reference's exact semantics: col>row OR s==0.0f -> -inf.
// ---------------------------------------------------------------------------
__global__ __launch_bounds__(256) void attn_kernel(float* __restrict__ out)
{
    __shared__ float Qs[QT][64];      // 8 KB
    __shared__ float Ks[64][64];      // 16 KB, float4-XOR-swizzled rows
    __shared__ float Vs[64][64];      // 16 KB, linear
    __shared__ float Ps[8][4][64];    // 8 KB  (total = 48 KB exactly)

    const int b   = blockIdx.y;
    const int p   = blockIdx.x;       // 0..31
    const int tid = threadIdx.x;
    const int w   = tid >> 5;
    const int l   = tid & 31;
    const int sw  = l & 15;           // swizzle key for this lane's K rows

    const float* qb = g_q + b * TT * HH;
    const float* kb = g_k + b * TT * HH;
    const float* vb = g_v + b * TT * HH;
    float*       ob = out + b * TT * HH;

    // per-thread tile-chunk coords: 4 float4 chunks per array
    int crow[4], cc4[4];
#pragma unroll
    for (int i = 0; i < 4; i++) {
        const int chunk = tid + i * 256;      // 0..1023
        crow[i] = chunk >> 4;
        cc4[i]  = chunk & 15;
    }

    for (int phase = 0; phase < 2; phase++) {
        const int qt = phase ? (63 - p) : p;
        const int qs = qt * QT;

        __syncthreads();   // previous phase fully done with smem

        for (int idx = tid; idx < QT * 64; idx += 256)
            Qs[idx >> 6][idx & 63] = qb[(qs + (idx >> 6)) * HH + (idx & 63)];

        float m[4], lsum[4], acc0[4], acc1[4];
#pragma unroll
        for (int i = 0; i < 4; i++) {
            m[i] = -INFINITY; lsum[i] = 0.f; acc0[i] = 0.f; acc1[i] = 0.f;
        }

        const int nkb = (qs + QT + 63) / 64;

        // prefetch tile 0 into registers
        float4 kr[4], vr[4];
#pragma unroll
        for (int i = 0; i < 4; i++) {
            kr[i] = *(const float4*)&kb[(crow[i]) * HH + cc4[i] * 4];
            vr[i] = *(const float4*)&vb[(crow[i]) * HH + cc4[i] * 4];
        }
        __syncthreads();   // Qs written; smem free
#pragma unroll
        for (int i = 0; i < 4; i++) {
            *(float4*)&Ks[crow[i]][(cc4[i] ^ (crow[i] & 15)) * 4] = kr[i];
            *(float4*)&Vs[crow[i]][cc4[i] * 4]                    = vr[i];
        }
        __syncthreads();

        for (int t = 0; t < nkb; t++) {
            // issue prefetch of next tile (hidden behind compute)
            if (t + 1 < nkb) {
#pragma unroll
                for (int i = 0; i < 4; i++) {
                    const int r = (t + 1) * 64 + crow[i];
                    kr[i] = *(const float4*)&kb[r * HH + cc4[i] * 4];
                    vr[i] = *(const float4*)&vb[r * HH + cc4[i] * 4];
                }
            }

            // ---- scores ----
            float s0[4] = {0.f, 0.f, 0.f, 0.f};
            float s1[4] = {0.f, 0.f, 0.f, 0.f};
#pragma unroll
            for (int c4 = 0; c4 < 16; c4++) {
                const int pc = (c4 ^ sw) * 4;
                float4 k0 = *(const float4*)&Ks[l][pc];
                float4 k1 = *(const float4*)&Ks[l + 32][pc];
#pragma unroll
                for (int i = 0; i < 4; i++) {
                    float4 q4 = *(const float4*)&Qs[(w << 2) + i][c4 * 4];
                    s0[i] += q4.x * k0.x + q4.y * k0.y + q4.z * k0.z + q4.w * k0.w;
                    s1[i] += q4.x * k1.x + q4.y * k1.y + q4.z * k1.z + q4.w * k1.w;
                }
            }

            const int col0 = t * 64 + l;
            const int col1 = col0 + 32;

#pragma unroll
            for (int i = 0; i < 4; i++) {
                const int rowg = qs + (w << 2) + i;
                float sc0 = s0[i] * 0.125f;
                float sc1 = s1[i] * 0.125f;
                if (col0 > rowg || sc0 == 0.0f) sc0 = -INFINITY;
                if (col1 > rowg || sc1 == 0.0f) sc1 = -INFINITY;

                float rmax = fmaxf(sc0, sc1);
#pragma unroll
                for (int off = 16; off > 0; off >>= 1)
                    rmax = fmaxf(rmax, __shfl_xor_sync(0xffffffffu, rmax, off));

                const float mnew = fmaxf(m[i], rmax);
                const float f    = __expf(m[i] - mnew);
                const float p0   = __expf(sc0 - mnew);
                const float p1   = __expf(sc1 - mnew);

                float psum = p0 + p1;
#pragma unroll
                for (int off = 16; off > 0; off >>= 1)
                    psum += __shfl_xor_sync(0xffffffffu, psum, off);

                lsum[i] = lsum[i] * f + psum;
                acc0[i] *= f;
                acc1[i] *= f;
                m[i] = mnew;

                Ps[w][i][l]      = p0;
                Ps[w][i][l + 32] = p1;
            }
            __syncwarp();

            // ---- P @ V : float4 broadcast P, scalar conflict-free V ----
#pragma unroll
            for (int j4 = 0; j4 < 16; j4++) {
                float pr[4][4];
#pragma unroll
                for (int i = 0; i < 4; i++) {
                    float4 p4 = *(const float4*)&Ps[w][i][j4 * 4];
                    pr[i][0] = p4.x; pr[i][1] = p4.y; pr[i][2] = p4.z; pr[i][3] = p4.w;
                }
#pragma unroll
                for (int jj = 0; jj < 4; jj++) {
                    const int j = j4 * 4 + jj;
                    const float v0 = Vs[j][l];
                    const float v1 = Vs[j][l + 32];
#pragma unroll
                    for (int i = 0; i < 4; i++) {
                        acc0[i] += pr[i][jj] * v0;
                        acc1[i] += pr[i][jj] * v1;
                    }
                }
            }
            __syncwarp();

            // ---- commit prefetched tile ----
            if (t + 1 < nkb) {
                __syncthreads();
#pragma unroll
                for (int i = 0; i < 4; i++) {
                    *(float4*)&Ks[crow[i]][(cc4[i] ^ (crow[i] & 15)) * 4] = kr[i];
                    *(float4*)&Vs[crow[i]][cc4[i] * 4]                    = vr[i];
                }
                __syncthreads();
            }
        }

#pragma unroll
        for (int i = 0; i < 4; i++) {
            const int rowg = qs + (w << 2) + i;
            const float inv = 1.0f / lsum[i];
            ob[rowg * HH + l]      = acc0[i] * inv;
            ob[rowg * HH + l + 32] = acc1[i] * inv;
        }
    }
}

// ---------------------------------------------------------------------------
extern "C" void kernel_launch(void* const* d_in, const int* in_sizes, int n_in,
                              void* d_out, int out_size)
{
    const float* x  = (const float*)d_in[0];
    const float* Wq = (const float*)d_in[1];
    const float* Wk = (const float*)d_in[2];
    const float* Wv = (const float*)d_in[3];
    float* out = (float*)d_out;

    proj_kernel<<<dim3(NROWS / 64, 3), 256>>>(x, Wq, Wk, Wv);
    attn_kernel<<<dim3(QT, BB), 256>>>(out);
}